// round 1
// baseline (speedup 1.0000x reference)
#include <cuda_runtime.h>

#define N_NODES 20000
#define N_EDGES 1280000
#define HD 64
#define NLAYERS 4
#define NGROUPS (N_EDGES / 8)

// ---------------- device scratch (no cudaMalloc allowed) ----------------
__device__ float g_h[N_NODES * HD];
__device__ float g_A[N_NODES * HD];   // h @ W1a + b1   (edge MLP, send half)
__device__ float g_B[N_NODES * HD];   // h @ W1b        (edge MLP, recv half)
__device__ float g_P[N_NODES * HD];   // h @ NW1a + nb1 (node MLP, h half)
__device__ float g_vg[N_NODES];       // velocity gate scalar
__device__ float g_coord[2][N_NODES * 3];
__device__ float g_vel[N_NODES * 3];
__device__ float g_ef[N_EDGES * HD];  // per-edge features (327.7 MB)
__device__ float g_trans[N_EDGES * 3];
__device__ int   g_cnt[N_NODES];
__device__ int   g_off[N_NODES + 1];
__device__ int   g_cur[N_NODES];
__device__ int   g_eid[N_EDGES];
__device__ float g_inv[N_NODES];

__device__ __forceinline__ float siluf(float x) {
    return x / (1.0f + __expf(-x));
}

// ---------------- packed f32x2 FMA (Blackwell; 2x fp32 MAC rate) ----------------
__device__ __forceinline__ unsigned long long ffma2(unsigned long long a,
                                                    unsigned long long b,
                                                    unsigned long long c) {
    unsigned long long d;
    asm("fma.rn.f32x2 %0, %1, %2, %3;" : "=l"(d) : "l"(a), "l"(b), "l"(c));
    return d;
}
__device__ __forceinline__ unsigned long long pk2(float lo, float hi) {
    unsigned long long d;
    asm("mov.b64 %0, {%1, %2};" : "=l"(d) : "f"(lo), "f"(hi));
    return d;
}
__device__ __forceinline__ float2 upk2(unsigned long long v) {
    float2 r;
    asm("mov.b64 {%0, %1}, %2;" : "=f"(r.x), "=f"(r.y) : "l"(v));
    return r;
}

// ---------------- setup kernels ----------------
__global__ void k_init(const float* __restrict__ inputs,
                       const float* __restrict__ emb_w,
                       const float* __restrict__ emb_b) {
    int idx = blockIdx.x * blockDim.x + threadIdx.x;
    if (idx >= N_NODES * HD) return;
    int n = idx >> 6, j = idx & 63;
    float vx = inputs[n * 6 + 3], vy = inputs[n * 6 + 4], vz = inputs[n * 6 + 5];
    float sp = sqrtf(vx * vx + vy * vy + vz * vz);
    g_h[idx] = sp * emb_w[j] + emb_b[j];
    if (j < 3) {
        g_coord[0][n * 3 + j] = inputs[n * 6 + j];
        g_vel[n * 3 + j] = inputs[n * 6 + 3 + j];
    }
    if (idx < N_NODES) g_cnt[idx] = 0;
}

__global__ void k_hist(const int* __restrict__ recv) {
    int e = blockIdx.x * blockDim.x + threadIdx.x;
    if (e < N_EDGES) atomicAdd(&g_cnt[recv[e]], 1);
}

__global__ void k_scan() {  // single block, 1024 threads
    __shared__ int part[1024];
    const int CH = (N_NODES + 1023) / 1024;  // 20
    int t = threadIdx.x;
    int s = 0;
    for (int i = 0; i < CH; i++) {
        int idx = t * CH + i;
        if (idx < N_NODES) s += g_cnt[idx];
    }
    part[t] = s;
    __syncthreads();
    for (int d = 1; d < 1024; d <<= 1) {
        int v = (t >= d) ? part[t - d] : 0;
        __syncthreads();
        part[t] += v;
        __syncthreads();
    }
    int run = (t == 0) ? 0 : part[t - 1];
    for (int i = 0; i < CH; i++) {
        int idx = t * CH + i;
        if (idx < N_NODES) {
            g_off[idx] = run;
            g_cur[idx] = run;
            int c = g_cnt[idx];
            g_inv[idx] = 1.0f / fmaxf((float)c, 1.0f);
            run += c;
            if (idx == N_NODES - 1) g_off[N_NODES] = run;
        }
    }
}

__global__ void k_fill(const int* __restrict__ recv) {
    int e = blockIdx.x * blockDim.x + threadIdx.x;
    if (e >= N_EDGES) return;
    int p = atomicAdd(&g_cur[recv[e]], 1);
    g_eid[p] = e;
}

// ---------------- per-layer node precompute: A, B, P, v_gate ----------------
__global__ void __launch_bounds__(256) k_node_pre(
    const float* __restrict__ w1a, const float* __restrict__ w1b,
    const float* __restrict__ b1,
    const float* __restrict__ nw1a, const float* __restrict__ nb1,
    const float* __restrict__ vw1, const float* __restrict__ vb1,
    const float* __restrict__ vw2, const float* __restrict__ vb2) {
    __shared__ float sH[8][68];
    int warp = threadIdx.x >> 5, lane = threadIdx.x & 31;
    int n = blockIdx.x * 8 + warp;
    if (n >= N_NODES) return;
    sH[warp][lane] = g_h[n * 64 + lane];
    sH[warp][lane + 32] = g_h[n * 64 + lane + 32];
    __syncwarp();
    float aA = b1[lane], aA2 = b1[lane + 32];
    float aB = 0.f, aB2 = 0.f;
    float aP = nb1[lane], aP2 = nb1[lane + 32];
    float aV = vb1[lane], aV2 = vb1[lane + 32];
#pragma unroll 4
    for (int k = 0; k < 64; k++) {
        float hv = sH[warp][k];
        aA += hv * w1a[k * 64 + lane];    aA2 += hv * w1a[k * 64 + lane + 32];
        aB += hv * w1b[k * 64 + lane];    aB2 += hv * w1b[k * 64 + lane + 32];
        aP += hv * nw1a[k * 64 + lane];   aP2 += hv * nw1a[k * 64 + lane + 32];
        aV += hv * vw1[k * 64 + lane];    aV2 += hv * vw1[k * 64 + lane + 32];
    }
    g_A[n * 64 + lane] = aA; g_A[n * 64 + lane + 32] = aA2;
    g_B[n * 64 + lane] = aB; g_B[n * 64 + lane + 32] = aB2;
    g_P[n * 64 + lane] = aP; g_P[n * 64 + lane + 32] = aP2;
    float q = siluf(aV), q2 = siluf(aV2);
    float part = q * vw2[lane] + q2 * vw2[lane + 32];
#pragma unroll
    for (int o = 16; o; o >>= 1) part += __shfl_xor_sync(0xffffffffu, part, o);
    if (lane == 0) g_vg[n] = part + vb2[0];
}

// ---------------- edge kernel: the FLOP hotspot ----------------
// One warp handles 8 edges at a time. Two 64x64 GEMMs done with packed
// fma.rn.f32x2: accumulator pair = (even-k partial, odd-k partial) for the
// same output element, so v-pairs and w-pairs come straight from smem with
// zero packing movs.
#define WT 68    // padded row stride for transposed weights (odd/4 -> conflict-free LDS.128)
#define EFST 68  // padded per-edge feature row
#define SMEM_EDGE_FLOATS (4352 * 3 + 256)
#define SMEM_EDGE_BYTES (SMEM_EDGE_FLOATS * 4)

__global__ void __launch_bounds__(256) k_edge(
    const int* __restrict__ send, const int* __restrict__ recv,
    const float* __restrict__ w2, const float* __restrict__ b2,
    const float* __restrict__ c1, const float* __restrict__ cb1,
    const float* __restrict__ cout, const float* __restrict__ w1c,
    int parity) {
    extern __shared__ float sm[];
    float* sW2T = sm;            // 64*68
    float* sC1T = sm + 4352;     // 64*68
    float* sEFb = sm + 8704;     // 8 warps * 8 edges * 68
    float* sb2 = sm + 13056;
    float* scb1 = sm + 13120;
    float* scout = sm + 13184;
    float* sw1c = sm + 13248;

    for (int i = threadIdx.x; i < 4096; i += 256) {
        int k = i >> 6, j = i & 63;
        sW2T[j * WT + k] = w2[i];
        sC1T[j * WT + k] = c1[i];
    }
    if (threadIdx.x < 64) {
        int j = threadIdx.x;
        sb2[j] = b2[j]; scb1[j] = cb1[j]; scout[j] = cout[j]; sw1c[j] = w1c[j];
    }
    __syncthreads();

    const float* coord = g_coord[parity];
    int warp = threadIdx.x >> 5, lane = threadIdx.x & 31;
    float* sEF = sEFb + warp * (8 * EFST);
    float w1cj = sw1c[lane], w1cj2 = sw1c[lane + 32];
    float bj = sb2[lane], bj2 = sb2[lane + 32];
    float cbj = scb1[lane], cbj2 = scb1[lane + 32];
    float coj = scout[lane], coj2 = scout[lane + 32];

    const ulonglong2* w2r = (const ulonglong2*)&sW2T[lane * WT];
    const ulonglong2* w2r2 = (const ulonglong2*)&sW2T[(lane + 32) * WT];
    const ulonglong2* c1r = (const ulonglong2*)&sC1T[lane * WT];
    const ulonglong2* c1r2 = (const ulonglong2*)&sC1T[(lane + 32) * WT];

    for (int grp = blockIdx.x * 8 + warp; grp < NGROUPS; grp += gridDim.x * 8) {
        int e0 = grp * 8;
        int sIdx = 0, rIdx = 0;
        float dx = 0.f, dy = 0.f, dz = 0.f, rad = 0.f;
        if (lane < 8) {
            int e = e0 + lane;
            sIdx = send[e];
            rIdx = recv[e];
            dx = coord[sIdx * 3 + 0] - coord[rIdx * 3 + 0];
            dy = coord[sIdx * 3 + 1] - coord[rIdx * 3 + 1];
            dz = coord[sIdx * 3 + 2] - coord[rIdx * 3 + 2];
            rad = dx * dx + dy * dy + dz * dz;
        }
        // ---- layer-1 (hoisted): ef1 = silu(A[s] + B[r] + rad*w1c) ----
#pragma unroll
        for (int e = 0; e < 8; e++) {
            int s = __shfl_sync(0xffffffffu, sIdx, e);
            int r = __shfl_sync(0xffffffffu, rIdx, e);
            float rd = __shfl_sync(0xffffffffu, rad, e);
            float z = g_A[s * 64 + lane] + g_B[r * 64 + lane] + rd * w1cj;
            float z2 = g_A[s * 64 + lane + 32] + g_B[r * 64 + lane + 32] + rd * w1cj2;
            sEF[e * EFST + lane] = siluf(z);
            sEF[e * EFST + lane + 32] = siluf(z2);
        }
        __syncwarp();

        // ---- GEMM1: ef = silu(ef1 @ W2 + b2) ----
        unsigned long long a0[8], a1[8];
#pragma unroll
        for (int e = 0; e < 8; e++) { a0[e] = pk2(bj, 0.f); a1[e] = pk2(bj2, 0.f); }
#pragma unroll 4
        for (int t = 0; t < 16; t++) {
            ulonglong2 wa = w2r[t], wb = w2r2[t];
#pragma unroll
            for (int e = 0; e < 8; e++) {
                ulonglong2 v = *(const ulonglong2*)&sEF[e * EFST + 4 * t];
                a0[e] = ffma2(v.x, wa.x, a0[e]);
                a1[e] = ffma2(v.x, wb.x, a1[e]);
                a0[e] = ffma2(v.y, wa.y, a0[e]);
                a1[e] = ffma2(v.y, wb.y, a1[e]);
            }
        }
        __syncwarp();
#pragma unroll
        for (int e = 0; e < 8; e++) {
            float2 p = upk2(a0[e]);
            float2 q = upk2(a1[e]);
            float f = siluf(p.x + p.y);
            float f2 = siluf(q.x + q.y);
            sEF[e * EFST + lane] = f;
            sEF[e * EFST + lane + 32] = f2;
            g_ef[(e0 + e) * 64 + lane] = f;
            g_ef[(e0 + e) * 64 + lane + 32] = f2;
        }
        __syncwarp();

        // ---- GEMM2: g = silu(ef @ C1 + cb1); cm = g . cout ----
#pragma unroll
        for (int e = 0; e < 8; e++) { a0[e] = pk2(cbj, 0.f); a1[e] = pk2(cbj2, 0.f); }
#pragma unroll 4
        for (int t = 0; t < 16; t++) {
            ulonglong2 wa = c1r[t], wb = c1r2[t];
#pragma unroll
            for (int e = 0; e < 8; e++) {
                ulonglong2 v = *(const ulonglong2*)&sEF[e * EFST + 4 * t];
                a0[e] = ffma2(v.x, wa.x, a0[e]);
                a1[e] = ffma2(v.x, wb.x, a1[e]);
                a0[e] = ffma2(v.y, wa.y, a0[e]);
                a1[e] = ffma2(v.y, wb.y, a1[e]);
            }
        }
        float mycm = 0.f;
#pragma unroll
        for (int e = 0; e < 8; e++) {
            float2 p = upk2(a0[e]);
            float2 q = upk2(a1[e]);
            float g1 = siluf(p.x + p.y);
            float g2 = siluf(q.x + q.y);
            float part = g1 * coj + g2 * coj2;
#pragma unroll
            for (int o = 16; o; o >>= 1) part += __shfl_xor_sync(0xffffffffu, part, o);
            if (lane == e) mycm = part;
        }
        if (lane < 8) {
            int e = e0 + lane;
            g_trans[e * 3 + 0] = fminf(fmaxf(dx * mycm, -100.f), 100.f);
            g_trans[e * 3 + 1] = fminf(fmaxf(dy * mycm, -100.f), 100.f);
            g_trans[e * 3 + 2] = fminf(fmaxf(dz * mycm, -100.f), 100.f);
        }
        __syncwarp();
    }
}

// ---------------- per-layer node update (gather + node MLP + dyn update) ----------------
__global__ void __launch_bounds__(256) k_node(
    const float* __restrict__ nw1b, const float* __restrict__ nw2,
    const float* __restrict__ nb2, int parity) {
    __shared__ float sA[8][68];
    int warp = threadIdx.x >> 5, lane = threadIdx.x & 31;
    int n = blockIdx.x * 8 + warp;
    if (n >= N_NODES) return;
    int start = g_off[n];
    int deg = g_off[n + 1] - start;
    float aH = 0.f, aH2 = 0.f, ax = 0.f, ay = 0.f, az = 0.f;
    for (int base = 0; base < deg; base += 32) {
        int m = deg - base;
        if (m > 32) m = 32;
        int e = 0;
        if (lane < m) {
            e = g_eid[start + base + lane];
            ax += g_trans[e * 3 + 0];
            ay += g_trans[e * 3 + 1];
            az += g_trans[e * 3 + 2];
        }
        for (int t = 0; t < m; t++) {
            int ee = __shfl_sync(0xffffffffu, e, t);
            aH += g_ef[ee * 64 + lane];
            aH2 += g_ef[ee * 64 + lane + 32];
        }
    }
#pragma unroll
    for (int o = 16; o; o >>= 1) {
        ax += __shfl_xor_sync(0xffffffffu, ax, o);
        ay += __shfl_xor_sync(0xffffffffu, ay, o);
        az += __shfl_xor_sync(0xffffffffu, az, o);
    }
    sA[warp][lane] = aH;
    sA[warp][lane + 32] = aH2;
    __syncwarp();
    float aQ = g_P[n * 64 + lane], aQ2 = g_P[n * 64 + lane + 32];
#pragma unroll 4
    for (int k = 0; k < 64; k++) {
        float v = sA[warp][k];
        aQ += v * nw1b[k * 64 + lane];
        aQ2 += v * nw1b[k * 64 + lane + 32];
    }
    float t1 = siluf(aQ), t2 = siluf(aQ2);
    __syncwarp();
    sA[warp][lane] = t1;
    sA[warp][lane + 32] = t2;
    __syncwarp();
    float aO = nb2[lane] + g_h[n * 64 + lane];
    float aO2 = nb2[lane + 32] + g_h[n * 64 + lane + 32];
#pragma unroll 4
    for (int k = 0; k < 64; k++) {
        float v = sA[warp][k];
        aO += v * nw2[k * 64 + lane];
        aO2 += v * nw2[k * 64 + lane + 32];
    }
    g_h[n * 64 + lane] = aO;
    g_h[n * 64 + lane + 32] = aO2;
    if (lane < 3) {
        float iv = g_inv[n];
        float agg = (lane == 0) ? ax : ((lane == 1) ? ay : az);
        float vo = g_vel[n * 3 + lane];
        float vn = agg * iv + g_vg[n] * vo;
        g_vel[n * 3 + lane] = vn;
        g_coord[parity ^ 1][n * 3 + lane] = g_coord[parity][n * 3 + lane] + vn;
    }
}

__global__ void k_out(float* __restrict__ out) {
    int idx = blockIdx.x * blockDim.x + threadIdx.x;
    if (idx >= N_NODES * 3) return;
    int n = idx / 3, c = idx % 3;
    out[n * 6 + c] = g_coord[0][idx];       // after 4 layers, coord lives in buf 0
    out[n * 6 + 3 + c] = g_vel[idx];
}

// ---------------- host launcher ----------------
extern "C" void kernel_launch(void* const* d_in, const int* in_sizes, int n_in,
                              void* d_out, int out_size) {
    const float* inputs = (const float*)d_in[0];
    // d_in[1] = node_masks (all ones, unused)
    const int* send = (const int*)d_in[2];
    const int* recv = (const int*)d_in[3];
    const float* emb_w = (const float*)d_in[4];
    const float* emb_b = (const float*)d_in[5];
    const float* ew1 = (const float*)d_in[6];   // (L,129,64)
    const float* eb1 = (const float*)d_in[7];   // (L,64)
    const float* ew2 = (const float*)d_in[8];   // (L,64,64)
    const float* eb2 = (const float*)d_in[9];
    const float* nw1 = (const float*)d_in[10];  // (L,128,64)
    const float* nb1 = (const float*)d_in[11];
    const float* nw2 = (const float*)d_in[12];  // (L,64,64)
    const float* nb2 = (const float*)d_in[13];
    const float* cw1 = (const float*)d_in[14];  // (L,64,64)
    const float* cb1 = (const float*)d_in[15];
    const float* cwo = (const float*)d_in[16];  // (L,64,1)
    const float* vw1 = (const float*)d_in[17];  // (L,64,64)
    const float* vb1 = (const float*)d_in[18];
    const float* vw2 = (const float*)d_in[19];  // (L,64,1)
    const float* vb2 = (const float*)d_in[20];  // (L,1)
    float* out = (float*)d_out;

    cudaFuncSetAttribute(k_edge, cudaFuncAttributeMaxDynamicSharedMemorySize,
                         SMEM_EDGE_BYTES);

    k_init<<<(N_NODES * HD + 255) / 256, 256>>>(inputs, emb_w, emb_b);
    k_hist<<<(N_EDGES + 511) / 512, 512>>>(recv);
    k_scan<<<1, 1024>>>();
    k_fill<<<(N_EDGES + 511) / 512, 512>>>(recv);

    for (int l = 0; l < NLAYERS; l++) {
        int par = l & 1;
        k_node_pre<<<(N_NODES + 7) / 8, 256>>>(
            ew1 + l * 8256, ew1 + l * 8256 + 4096, eb1 + l * 64,
            nw1 + l * 8192, nb1 + l * 64,
            vw1 + l * 4096, vb1 + l * 64, vw2 + l * 64, vb2 + l);
        k_edge<<<608, 256, SMEM_EDGE_BYTES>>>(
            send, recv, ew2 + l * 4096, eb2 + l * 64,
            cw1 + l * 4096, cb1 + l * 64, cwo + l * 64,
            ew1 + l * 8256 + 8192, par);
        k_node<<<(N_NODES + 7) / 8, 256>>>(
            nw1 + l * 8192 + 4096, nw2 + l * 4096, nb2 + l * 64, par);
    }
    k_out<<<(N_NODES * 3 + 255) / 256, 256>>>(out);
}